// round 14
// baseline (speedup 1.0000x reference)
#include <cuda_runtime.h>
#include <cuda_fp16.h>
#include <cstdint>
#include <cstddef>

// ---------------------------------------------------------------------------
// Problem dims (fixed by the dataset)
// ---------------------------------------------------------------------------
#define DIM_M 8192   // B*S = 4*2048
#define DIM_N 4096   // O
#define DIM_K 4096   // I

// GEMM tiling: CTA 128x128x64, 4 warps (2x2), warp tile 64x64, 2 CTAs/SM
#define BM 128
#define BN 128
#define BK 64
#define NKITER (DIM_K / BK)     // 64
#define STAGES 3
#define THREADS 128

#define STAGE_A_BYTES (BM * BK * 2)             // 16384
#define STAGE_B_BYTES (BN * BK * 2)             // 16384
#define STAGE_BYTES   (STAGE_A_BYTES + STAGE_B_BYTES)   // 32768
#define SMEM_TOTAL    (STAGES * STAGE_BYTES)    // 98304 -> 2 CTAs/SM

// fused conversion kernel block split
#define XCONV_BLOCKS ((DIM_M * DIM_K / 4) / 256)     // 32768
#define WDEQ_BLOCKS  ((DIM_N * DIM_K / 8) / 256)     // 8192

// ---------------------------------------------------------------------------
// Device scratch (allocation-free rule: __device__ globals)
// ---------------------------------------------------------------------------
__device__ __align__(256) __half g_X16[(size_t)DIM_M * DIM_K];  // 64 MB
__device__ __align__(256) __half g_W16[(size_t)DIM_N * DIM_K];  // 32 MB

__constant__ float c_nf4[16] = {
    -1.0f, -0.6961928009986877f, -0.5250730514526367f, -0.39491748809814453f,
    -0.28444138169288635f, -0.18477343022823334f, -0.09105003625154495f, 0.0f,
    0.07958029955625534f, 0.16093020141124725f, 0.24611230194568634f,
    0.33791524171829224f, 0.44070982933044434f, 0.5626170039176941f,
    0.7229568362236023f, 1.0f};

// ---------------------------------------------------------------------------
// PTX helpers (baseline PTX only -- NOTHING sm_103a-suffix-specific)
// ---------------------------------------------------------------------------
__device__ __forceinline__ uint32_t smem_u32(const void* p) {
    uint32_t a;
    asm("{ .reg .u64 t; cvta.to.shared.u64 t, %1; cvt.u32.u64 %0, t; }"
        : "=r"(a) : "l"(p));
    return a;
}

__device__ __forceinline__ void cp_async16(uint32_t dst, const void* src) {
    asm volatile("cp.async.cg.shared.global [%0], [%1], 16;\n"
                 :: "r"(dst), "l"(src));
}
__device__ __forceinline__ void cp_commit() {
    asm volatile("cp.async.commit_group;\n" ::: "memory");
}
template <int N>
__device__ __forceinline__ void cp_wait_group() {
    asm volatile("cp.async.wait_group %0;\n" :: "n"(N) : "memory");
}

__device__ __forceinline__ void ldmatrix_x4(uint32_t* r, uint32_t addr) {
    asm volatile(
        "ldmatrix.sync.aligned.m8n8.x4.shared.b16 {%0,%1,%2,%3}, [%4];\n"
        : "=r"(r[0]), "=r"(r[1]), "=r"(r[2]), "=r"(r[3]) : "r"(addr));
}

__device__ __forceinline__ void mma_16816(float* c, const uint32_t* a,
                                          uint32_t b0, uint32_t b1) {
    asm volatile(
        "mma.sync.aligned.m16n8k16.row.col.f32.f16.f16.f32 "
        "{%0,%1,%2,%3}, {%4,%5,%6,%7}, {%8,%9}, {%0,%1,%2,%3};\n"
        : "+f"(c[0]), "+f"(c[1]), "+f"(c[2]), "+f"(c[3])
        : "r"(a[0]), "r"(a[1]), "r"(a[2]), "r"(a[3]), "r"(b0), "r"(b1));
}

// ---------------------------------------------------------------------------
// Kernel 1 (fused): x fp32 -> fp16  AND  NF4 + double-quant dequant -> fp16 W
// ---------------------------------------------------------------------------
__global__ void convert_fused_kernel(const float* __restrict__ x,
                                     const int* __restrict__ codes,
                                     const int* __restrict__ amc,
                                     const float* __restrict__ ams,
                                     const float* __restrict__ amo) {
    const int bx = blockIdx.x;
    if (bx < XCONV_BLOCKS) {
        int i = bx * 256 + threadIdx.x;          // one float4 each, exact cover
        float4 v = reinterpret_cast<const float4*>(x)[i];
        __half2 a = __floats2half2_rn(v.x, v.y);
        __half2 b = __floats2half2_rn(v.z, v.w);
        uint2 o;
        o.x = *reinterpret_cast<unsigned*>(&a);
        o.y = *reinterpret_cast<unsigned*>(&b);
        reinterpret_cast<uint2*>(g_X16)[i] = o;
    } else {
        __shared__ float lut[16];
        if (threadIdx.x < 16) lut[threadIdx.x] = c_nf4[threadIdx.x];
        __syncthreads();

        int gid = (bx - XCONV_BLOCKS) * 256 + threadIdx.x;  // 8 codes each
        int b = gid >> 3;                        // 64-elem block index
        float am = fmaf((float)amc[b] * (1.0f / 255.0f), ams[b >> 8], amo[0]);

        const int4* c4 = reinterpret_cast<const int4*>(codes) + (size_t)gid * 2;
        int4 c0 = c4[0];
        int4 c1 = c4[1];

        __half2 p0 = __floats2half2_rn(lut[c0.x] * am, lut[c0.y] * am);
        __half2 p1 = __floats2half2_rn(lut[c0.z] * am, lut[c0.w] * am);
        __half2 p2 = __floats2half2_rn(lut[c1.x] * am, lut[c1.y] * am);
        __half2 p3 = __floats2half2_rn(lut[c1.z] * am, lut[c1.w] * am);

        uint4 o;
        o.x = *reinterpret_cast<unsigned*>(&p0);
        o.y = *reinterpret_cast<unsigned*>(&p1);
        o.z = *reinterpret_cast<unsigned*>(&p2);
        o.w = *reinterpret_cast<unsigned*>(&p3);
        reinterpret_cast<uint4*>(g_W16)[gid] = o;
    }
}

// ---------------------------------------------------------------------------
// Kernel 2: mma.sync GEMM  out[M,N] = X16[M,K] * W16[N,K]^T + bias
//   CTA 128x128x64, 4 warps (2x2), warp tile 64x64, 3-stage cp.async,
//   2 CTAs/SM. The wait+barrier sit MID-iteration (after the ks0 mma batch),
//   so warps flow from ks3 of iter it-1 straight into ks0 of iter it with
//   the tensor pipe never draining at the boundary. wait_group<0> there has
//   a full iteration of slack (group committed mid previous iteration).
// ---------------------------------------------------------------------------
__device__ __forceinline__ void load_half(uint32_t st, int tid,
                                          const __half* __restrict__ g) {
#pragma unroll
    for (int j = 0; j < 8; j++) {                 // 128 rows x 128B
        int c = tid + j * THREADS;
        int row = c >> 3, kk = c & 7;
        uint32_t sw = (uint32_t)(row * 128) + ((uint32_t)(kk ^ (row & 7)) * 16);
        cp_async16(st + sw, g + (size_t)row * DIM_K + kk * 8);
    }
}

__global__ __launch_bounds__(THREADS, 2)
void gemm_kernel(const float* __restrict__ bias, float* __restrict__ out) {
    extern __shared__ __align__(1024) char smem[];
    const uint32_t smem_base = smem_u32(smem);
    const int tid = threadIdx.x;
    const int wid = tid >> 5, lane = tid & 31;
    const int warpM = wid & 1;         // 0..1, 64 rows each
    const int warpN = wid >> 1;        // 0..1, 64 cols each
    const int mBase = blockIdx.y * BM;
    const int nBase = blockIdx.x * BN;

    const __half* gA = g_X16 + (size_t)mBase * DIM_K;
    const __half* gB = g_W16 + (size_t)nBase * DIM_K;

    // per-thread ldmatrix row/half decomposition
    const uint32_t rowA = (uint32_t)(warpM * 64 + (lane & 15));
    const uint32_t halfA = (uint32_t)(lane >> 4);
    const uint32_t swzA = rowA & 7;
    const uint32_t rowB = (uint32_t)(warpN * 64 + (lane & 7) + 8 * (lane >> 4));
    const uint32_t halfB = (uint32_t)((lane >> 3) & 1);
    const uint32_t swzB = rowB & 7;

    float acc[4][8][4];                 // [mt][nt][frag] : 64x64 per warp
#pragma unroll
    for (int mt = 0; mt < 4; mt++)
#pragma unroll
        for (int nt = 0; nt < 8; nt++)
#pragma unroll
            for (int j = 0; j < 4; j++) acc[mt][nt][j] = 0.0f;

    // prologue: fill stages 0,1; one-time hard sync so iter-0 ks0 is valid
#pragma unroll
    for (int s = 0; s < STAGES - 1; s++) {
        const uint32_t st = smem_base + (uint32_t)s * STAGE_BYTES;
        load_half(st, tid, gA + s * BK);
        load_half(st + STAGE_A_BYTES, tid, gB + s * BK);
        cp_commit();
    }
    cp_wait_group<0>();
    __syncthreads();

    int s_comp = 0;                     // stage being computed (mod 3)
    int s_load = STAGES - 1;            // stage being filled   (mod 3)
    for (int it = 0; it < NKITER; it++) {
        const uint32_t stA = smem_base + (uint32_t)s_comp * STAGE_BYTES;
        const uint32_t stB = stA + STAGE_A_BYTES;
        if (++s_comp == STAGES) s_comp = 0;

        const uint32_t stL = smem_base + (uint32_t)s_load * STAGE_BYTES;
        const int ktL = it + STAGES - 1;
        const bool doLoad = ktL < NKITER;
        if (++s_load == STAGES) s_load = 0;

        uint32_t afrag[4][4];
        uint32_t bfrag[4][4];

#pragma unroll
        for (int ks = 0; ks < 4; ks++) {
            // frag loads for this ks. ks0 needs no preceding barrier: its
            // stage was filled 2 iters ago, drained by ALL threads at their
            // mid-(it-1) wait<0>, ordered by the mid-(it-1) barrier.
#pragma unroll
            for (int mt = 0; mt < 4; mt++) {
                uint32_t row = rowA + (uint32_t)(mt * 16);
                uint32_t addr = stA + row * 128 +
                                (((uint32_t)(ks * 2) + halfA) ^ swzA) * 16;
                ldmatrix_x4(afrag[mt], addr);
            }
#pragma unroll
            for (int i = 0; i < 4; i++) {
                uint32_t row = rowB + (uint32_t)(i * 16);
                uint32_t addr = stB + row * 128 +
                                (((uint32_t)(ks * 2) + halfB) ^ swzB) * 16;
                ldmatrix_x4(bfrag[i], addr);
            }
#pragma unroll
            for (int mt = 0; mt < 4; mt++) {
#pragma unroll
                for (int nt = 0; nt < 8; nt++) {
                    mma_16816(acc[mt][nt], afrag[mt],
                              bfrag[nt >> 1][(nt & 1) * 2],
                              bfrag[nt >> 1][(nt & 1) * 2 + 1]);
                }
            }
            if (ks == 0) {
                // mid-iteration sync point, hidden under the ks0 mma drain:
                // wait<0> drains the group committed mid-(it-1) (full iter of
                // slack); barrier separates everyone's drains from the writes
                // below AND from next iteration's ks0 reads.
                cp_wait_group<0>();
                __syncthreads();
                if (doLoad)
                    load_half(stL, tid, gA + ktL * BK);
            }
            if (ks == 1 && doLoad) {
                load_half(stL + STAGE_A_BYTES, tid, gB + ktL * BK);
                cp_commit();
            }
        }
    }

    // ------------------ epilogue: bias + direct float2 stores ---------------
#pragma unroll
    for (int nt = 0; nt < 8; nt++) {
        const int col0 = nBase + warpN * 64 + nt * 8 + (lane & 3) * 2;
        const float2 bv = *reinterpret_cast<const float2*>(bias + col0);
#pragma unroll
        for (int mt = 0; mt < 4; mt++) {
            const int row0 = mBase + warpM * 64 + mt * 16 + (lane >> 2);
            float2 v0 = make_float2(acc[mt][nt][0] + bv.x, acc[mt][nt][1] + bv.y);
            float2 v1 = make_float2(acc[mt][nt][2] + bv.x, acc[mt][nt][3] + bv.y);
            *reinterpret_cast<float2*>(out + (size_t)row0 * DIM_N + col0) = v0;
            *reinterpret_cast<float2*>(out + (size_t)(row0 + 8) * DIM_N + col0) = v1;
        }
    }
}

// ---------------------------------------------------------------------------
// Launch
// ---------------------------------------------------------------------------
extern "C" void kernel_launch(void* const* d_in, const int* in_sizes, int n_in,
                              void* d_out, int out_size) {
    const float* x       = (const float*)d_in[0];
    const int*   w_codes = (const int*)  d_in[1];
    const int*   amc     = (const int*)  d_in[2];
    const float* ams     = (const float*)d_in[3];
    const float* amo     = (const float*)d_in[4];
    const float* bias    = (const float*)d_in[5];
    float* out = (float*)d_out;

    convert_fused_kernel<<<XCONV_BLOCKS + WDEQ_BLOCKS, 256>>>(x, w_codes, amc,
                                                              ams, amo);

    static int smem_set = 0;
    if (!smem_set) {
        cudaFuncSetAttribute(gemm_kernel,
                             cudaFuncAttributeMaxDynamicSharedMemorySize,
                             SMEM_TOTAL);
        smem_set = 1;
    }
    dim3 grid(DIM_N / BN, DIM_M / BM);
    gemm_kernel<<<grid, THREADS, SMEM_TOTAL>>>(bias, out);
}

// round 15
// speedup vs baseline: 1.4943x; 1.4943x over previous
#include <cuda_runtime.h>
#include <cuda_fp16.h>
#include <cstdint>
#include <cstddef>

// ---------------------------------------------------------------------------
// Problem dims (fixed by the dataset)
// ---------------------------------------------------------------------------
#define DIM_M 8192   // B*S = 4*2048
#define DIM_N 4096   // O
#define DIM_K 4096   // I

// GEMM tiling: CTA 128x128x64, 4 warps (2x2), warp tile 64x64, 2 CTAs/SM
#define BM 128
#define BN 128
#define BK 64
#define NKITER (DIM_K / BK)     // 64
#define STAGES 3
#define THREADS 128

#define STAGE_A_BYTES (BM * BK * 2)             // 16384
#define STAGE_B_BYTES (BN * BK * 2)             // 16384
#define STAGE_BYTES   (STAGE_A_BYTES + STAGE_B_BYTES)   // 32768
#define SMEM_TOTAL    (STAGES * STAGE_BYTES)    // 98304 -> 2 CTAs/SM

// fused conversion kernel block split
#define XCONV_BLOCKS ((DIM_M * DIM_K / 4) / 256)     // 32768
#define WDEQ_BLOCKS  ((DIM_N * DIM_K / 8) / 256)     // 8192

// ---------------------------------------------------------------------------
// Device scratch (allocation-free rule: __device__ globals)
// ---------------------------------------------------------------------------
__device__ __align__(256) __half g_X16[(size_t)DIM_M * DIM_K];  // 64 MB
__device__ __align__(256) __half g_W16[(size_t)DIM_N * DIM_K];  // 32 MB

__constant__ float c_nf4[16] = {
    -1.0f, -0.6961928009986877f, -0.5250730514526367f, -0.39491748809814453f,
    -0.28444138169288635f, -0.18477343022823334f, -0.09105003625154495f, 0.0f,
    0.07958029955625534f, 0.16093020141124725f, 0.24611230194568634f,
    0.33791524171829224f, 0.44070982933044434f, 0.5626170039176941f,
    0.7229568362236023f, 1.0f};

// ---------------------------------------------------------------------------
// PTX helpers (baseline PTX only -- NOTHING sm_103a-suffix-specific)
// ---------------------------------------------------------------------------
__device__ __forceinline__ uint32_t smem_u32(const void* p) {
    uint32_t a;
    asm("{ .reg .u64 t; cvta.to.shared.u64 t, %1; cvt.u32.u64 %0, t; }"
        : "=r"(a) : "l"(p));
    return a;
}

__device__ __forceinline__ void cp_async16(uint32_t dst, const void* src) {
    asm volatile("cp.async.cg.shared.global [%0], [%1], 16;\n"
                 :: "r"(dst), "l"(src));
}
__device__ __forceinline__ void cp_commit() {
    asm volatile("cp.async.commit_group;\n" ::: "memory");
}
template <int N>
__device__ __forceinline__ void cp_wait_group() {
    asm volatile("cp.async.wait_group %0;\n" :: "n"(N) : "memory");
}

__device__ __forceinline__ void ldmatrix_x4(uint32_t* r, uint32_t addr) {
    asm volatile(
        "ldmatrix.sync.aligned.m8n8.x4.shared.b16 {%0,%1,%2,%3}, [%4];\n"
        : "=r"(r[0]), "=r"(r[1]), "=r"(r[2]), "=r"(r[3]) : "r"(addr));
}

__device__ __forceinline__ void mma_16816(float* c, const uint32_t* a,
                                          uint32_t b0, uint32_t b1) {
    asm volatile(
        "mma.sync.aligned.m16n8k16.row.col.f32.f16.f16.f32 "
        "{%0,%1,%2,%3}, {%4,%5,%6,%7}, {%8,%9}, {%0,%1,%2,%3};\n"
        : "+f"(c[0]), "+f"(c[1]), "+f"(c[2]), "+f"(c[3])
        : "r"(a[0]), "r"(a[1]), "r"(a[2]), "r"(a[3]), "r"(b0), "r"(b1));
}

// ---------------------------------------------------------------------------
// Kernel 1 (fused): x fp32 -> fp16  AND  NF4 + double-quant dequant -> fp16 W
// ---------------------------------------------------------------------------
__global__ void convert_fused_kernel(const float* __restrict__ x,
                                     const int* __restrict__ codes,
                                     const int* __restrict__ amc,
                                     const float* __restrict__ ams,
                                     const float* __restrict__ amo) {
    const int bx = blockIdx.x;
    if (bx < XCONV_BLOCKS) {
        int i = bx * 256 + threadIdx.x;          // one float4 each, exact cover
        float4 v = reinterpret_cast<const float4*>(x)[i];
        __half2 a = __floats2half2_rn(v.x, v.y);
        __half2 b = __floats2half2_rn(v.z, v.w);
        uint2 o;
        o.x = *reinterpret_cast<unsigned*>(&a);
        o.y = *reinterpret_cast<unsigned*>(&b);
        reinterpret_cast<uint2*>(g_X16)[i] = o;
    } else {
        __shared__ float lut[16];
        if (threadIdx.x < 16) lut[threadIdx.x] = c_nf4[threadIdx.x];
        __syncthreads();

        int gid = (bx - XCONV_BLOCKS) * 256 + threadIdx.x;  // 8 codes each
        int b = gid >> 3;                        // 64-elem block index
        float am = fmaf((float)amc[b] * (1.0f / 255.0f), ams[b >> 8], amo[0]);

        const int4* c4 = reinterpret_cast<const int4*>(codes) + (size_t)gid * 2;
        int4 c0 = c4[0];
        int4 c1 = c4[1];

        __half2 p0 = __floats2half2_rn(lut[c0.x] * am, lut[c0.y] * am);
        __half2 p1 = __floats2half2_rn(lut[c0.z] * am, lut[c0.w] * am);
        __half2 p2 = __floats2half2_rn(lut[c1.x] * am, lut[c1.y] * am);
        __half2 p3 = __floats2half2_rn(lut[c1.z] * am, lut[c1.w] * am);

        uint4 o;
        o.x = *reinterpret_cast<unsigned*>(&p0);
        o.y = *reinterpret_cast<unsigned*>(&p1);
        o.z = *reinterpret_cast<unsigned*>(&p2);
        o.w = *reinterpret_cast<unsigned*>(&p3);
        reinterpret_cast<uint4*>(g_W16)[gid] = o;
    }
}

// ---------------------------------------------------------------------------
// Kernel 2: mma.sync GEMM  out[M,N] = X16[M,K] * W16[N,K]^T + bias
//   CTA 128x128x64, 4 warps (2x2), warp tile 64x64, 3-stage cp.async,
//   2 CTAs/SM. Round-12 schedule (the proven winner): wait<1> + barrier at
//   iteration top, LDSM batch per ks, cp.async halves issued after the ks0
//   and ks1 mma batches (hidden under tensor-pipe drain). 1-D banded grid:
//   8 M-tiles x 32 N-tiles per band for tighter wave L2 footprint.
// ---------------------------------------------------------------------------
__device__ __forceinline__ void load_half(uint32_t st, int tid,
                                          const __half* __restrict__ g) {
#pragma unroll
    for (int j = 0; j < 8; j++) {                 // 128 rows x 128B
        int c = tid + j * THREADS;
        int row = c >> 3, kk = c & 7;
        uint32_t sw = (uint32_t)(row * 128) + ((uint32_t)(kk ^ (row & 7)) * 16);
        cp_async16(st + sw, g + (size_t)row * DIM_K + kk * 8);
    }
}

__global__ __launch_bounds__(THREADS, 2)
void gemm_kernel(const float* __restrict__ bias, float* __restrict__ out) {
    extern __shared__ __align__(1024) char smem[];
    const uint32_t smem_base = smem_u32(smem);
    const int tid = threadIdx.x;
    const int wid = tid >> 5, lane = tid & 31;
    const int warpM = wid & 1;         // 0..1, 64 rows each
    const int warpN = wid >> 1;        // 0..1, 64 cols each

    // banded rasterization: band = 8 M-tiles tall, N fast within a band
    const int bid = blockIdx.x;
    const int mTile = ((bid >> 8) << 3) | (bid & 7);
    const int nTile = (bid >> 3) & 31;
    const int mBase = mTile * BM;
    const int nBase = nTile * BN;

    const __half* gA = g_X16 + (size_t)mBase * DIM_K;
    const __half* gB = g_W16 + (size_t)nBase * DIM_K;

    // per-thread ldmatrix row/half decomposition
    const uint32_t rowA = (uint32_t)(warpM * 64 + (lane & 15));
    const uint32_t halfA = (uint32_t)(lane >> 4);
    const uint32_t swzA = rowA & 7;
    const uint32_t rowB = (uint32_t)(warpN * 64 + (lane & 7) + 8 * (lane >> 4));
    const uint32_t halfB = (uint32_t)((lane >> 3) & 1);
    const uint32_t swzB = rowB & 7;

    float acc[4][8][4];                 // [mt][nt][frag] : 64x64 per warp
#pragma unroll
    for (int mt = 0; mt < 4; mt++)
#pragma unroll
        for (int nt = 0; nt < 8; nt++)
#pragma unroll
            for (int j = 0; j < 4; j++) acc[mt][nt][j] = 0.0f;

    // prologue: fill STAGES-1 stages
#pragma unroll
    for (int s = 0; s < STAGES - 1; s++) {
        const uint32_t st = smem_base + (uint32_t)s * STAGE_BYTES;
        load_half(st, tid, gA + s * BK);
        load_half(st + STAGE_A_BYTES, tid, gB + s * BK);
        cp_commit();
    }

    int s_comp = 0;                     // stage being computed (mod 3)
    int s_load = STAGES - 1;            // stage being filled   (mod 3)
    for (int it = 0; it < NKITER; it++) {
        cp_wait_group<STAGES - 2>();
        __syncthreads();

        const uint32_t stA = smem_base + (uint32_t)s_comp * STAGE_BYTES;
        const uint32_t stB = stA + STAGE_A_BYTES;
        if (++s_comp == STAGES) s_comp = 0;

        const uint32_t stL = smem_base + (uint32_t)s_load * STAGE_BYTES;
        const int ktL = it + STAGES - 1;
        const bool doLoad = ktL < NKITER;
        if (++s_load == STAGES) s_load = 0;

        uint32_t afrag[4][4];
        uint32_t bfrag[4][4];

#pragma unroll
        for (int ks = 0; ks < 4; ks++) {
            // frag loads for this ks (ks0 right after barrier; ks>0 hidden
            // under previous batch drain)
#pragma unroll
            for (int mt = 0; mt < 4; mt++) {
                uint32_t row = rowA + (uint32_t)(mt * 16);
                uint32_t addr = stA + row * 128 +
                                (((uint32_t)(ks * 2) + halfA) ^ swzA) * 16;
                ldmatrix_x4(afrag[mt], addr);
            }
#pragma unroll
            for (int i = 0; i < 4; i++) {
                uint32_t row = rowB + (uint32_t)(i * 16);
                uint32_t addr = stB + row * 128 +
                                (((uint32_t)(ks * 2) + halfB) ^ swzB) * 16;
                ldmatrix_x4(bfrag[i], addr);
            }
#pragma unroll
            for (int mt = 0; mt < 4; mt++) {
#pragma unroll
                for (int nt = 0; nt < 8; nt++) {
                    mma_16816(acc[mt][nt], afrag[mt],
                              bfrag[nt >> 1][(nt & 1) * 2],
                              bfrag[nt >> 1][(nt & 1) * 2 + 1]);
                }
            }
            // cp.async bursts AFTER a full mma batch: the tensor pipe drains
            // the batch (via issue backpressure) while the LSU issues these
            if (ks == 0 && doLoad)
                load_half(stL, tid, gA + ktL * BK);
            if (ks == 1) {
                if (doLoad)
                    load_half(stL + STAGE_A_BYTES, tid, gB + ktL * BK);
                cp_commit();            // one commit per iter, full stage
            }
        }
    }

    // ------------------ epilogue: bias + direct float2 stores ---------------
#pragma unroll
    for (int nt = 0; nt < 8; nt++) {
        const int col0 = nBase + warpN * 64 + nt * 8 + (lane & 3) * 2;
        const float2 bv = *reinterpret_cast<const float2*>(bias + col0);
#pragma unroll
        for (int mt = 0; mt < 4; mt++) {
            const int row0 = mBase + warpM * 64 + mt * 16 + (lane >> 2);
            float2 v0 = make_float2(acc[mt][nt][0] + bv.x, acc[mt][nt][1] + bv.y);
            float2 v1 = make_float2(acc[mt][nt][2] + bv.x, acc[mt][nt][3] + bv.y);
            *reinterpret_cast<float2*>(out + (size_t)row0 * DIM_N + col0) = v0;
            *reinterpret_cast<float2*>(out + (size_t)(row0 + 8) * DIM_N + col0) = v1;
        }
    }
}

// ---------------------------------------------------------------------------
// Launch
// ---------------------------------------------------------------------------
extern "C" void kernel_launch(void* const* d_in, const int* in_sizes, int n_in,
                              void* d_out, int out_size) {
    const float* x       = (const float*)d_in[0];
    const int*   w_codes = (const int*)  d_in[1];
    const int*   amc     = (const int*)  d_in[2];
    const float* ams     = (const float*)d_in[3];
    const float* amo     = (const float*)d_in[4];
    const float* bias    = (const float*)d_in[5];
    float* out = (float*)d_out;

    convert_fused_kernel<<<XCONV_BLOCKS + WDEQ_BLOCKS, 256>>>(x, w_codes, amc,
                                                              ams, amo);

    static int smem_set = 0;
    if (!smem_set) {
        cudaFuncSetAttribute(gemm_kernel,
                             cudaFuncAttributeMaxDynamicSharedMemorySize,
                             SMEM_TOTAL);
        smem_set = 1;
    }
    gemm_kernel<<<(DIM_N / BN) * (DIM_M / BM), THREADS, SMEM_TOTAL>>>(bias, out);
}

// round 16
// speedup vs baseline: 1.5451x; 1.0340x over previous
#include <cuda_runtime.h>
#include <cuda_fp16.h>
#include <cstdint>
#include <cstddef>

// ---------------------------------------------------------------------------
// Problem dims (fixed by the dataset)
// ---------------------------------------------------------------------------
#define DIM_M 8192   // B*S = 4*2048
#define DIM_N 4096   // O
#define DIM_K 4096   // I

// GEMM tiling: CTA 128x128x64, 4 warps (2x2), warp tile 64x64, 2 CTAs/SM
#define BM 128
#define BN 128
#define BK 64
#define NKITER (DIM_K / BK)     // 64
#define STAGES 3
#define THREADS 128

#define STAGE_A_BYTES (BM * BK * 2)             // 16384
#define STAGE_B_BYTES (BN * BK * 2)             // 16384
#define STAGE_BYTES   (STAGE_A_BYTES + STAGE_B_BYTES)   // 32768
#define SMEM_TOTAL    (STAGES * STAGE_BYTES)    // 98304 -> 2 CTAs/SM

// fused conversion kernel block split (x: 32B/thread, w: 8 codes/thread)
#define XCONV_BLOCKS ((DIM_M * DIM_K / 8) / 256)     // 16384
#define WDEQ_BLOCKS  ((DIM_N * DIM_K / 8) / 256)     // 8192

// ---------------------------------------------------------------------------
// Device scratch (allocation-free rule: __device__ globals)
// ---------------------------------------------------------------------------
__device__ __align__(256) __half g_X16[(size_t)DIM_M * DIM_K];  // 64 MB
__device__ __align__(256) __half g_W16[(size_t)DIM_N * DIM_K];  // 32 MB

__constant__ float c_nf4[16] = {
    -1.0f, -0.6961928009986877f, -0.5250730514526367f, -0.39491748809814453f,
    -0.28444138169288635f, -0.18477343022823334f, -0.09105003625154495f, 0.0f,
    0.07958029955625534f, 0.16093020141124725f, 0.24611230194568634f,
    0.33791524171829224f, 0.44070982933044434f, 0.5626170039176941f,
    0.7229568362236023f, 1.0f};

// ---------------------------------------------------------------------------
// PTX helpers (baseline PTX only -- NOTHING sm_103a-suffix-specific)
// ---------------------------------------------------------------------------
__device__ __forceinline__ uint32_t smem_u32(const void* p) {
    uint32_t a;
    asm("{ .reg .u64 t; cvta.to.shared.u64 t, %1; cvt.u32.u64 %0, t; }"
        : "=r"(a) : "l"(p));
    return a;
}

__device__ __forceinline__ void cp_async16(uint32_t dst, const void* src) {
    asm volatile("cp.async.cg.shared.global [%0], [%1], 16;\n"
                 :: "r"(dst), "l"(src));
}
__device__ __forceinline__ void cp_commit() {
    asm volatile("cp.async.commit_group;\n" ::: "memory");
}
template <int N>
__device__ __forceinline__ void cp_wait_group() {
    asm volatile("cp.async.wait_group %0;\n" :: "n"(N) : "memory");
}

__device__ __forceinline__ void ldmatrix_x4(uint32_t* r, uint32_t addr) {
    asm volatile(
        "ldmatrix.sync.aligned.m8n8.x4.shared.b16 {%0,%1,%2,%3}, [%4];\n"
        : "=r"(r[0]), "=r"(r[1]), "=r"(r[2]), "=r"(r[3]) : "r"(addr));
}

__device__ __forceinline__ void mma_16816(float* c, const uint32_t* a,
                                          uint32_t b0, uint32_t b1) {
    asm volatile(
        "mma.sync.aligned.m16n8k16.row.col.f32.f16.f16.f32 "
        "{%0,%1,%2,%3}, {%4,%5,%6,%7}, {%8,%9}, {%0,%1,%2,%3};\n"
        : "+f"(c[0]), "+f"(c[1]), "+f"(c[2]), "+f"(c[3])
        : "r"(a[0]), "r"(a[1]), "r"(a[2]), "r"(a[3]), "r"(b0), "r"(b1));
}

// ---------------------------------------------------------------------------
// Kernel 1 (fused): x fp32 -> fp16  AND  NF4 + double-quant dequant -> fp16 W
//   x path: 32 bytes (2x float4) per thread for higher DRAM efficiency
// ---------------------------------------------------------------------------
__global__ void convert_fused_kernel(const float* __restrict__ x,
                                     const int* __restrict__ codes,
                                     const int* __restrict__ amc,
                                     const float* __restrict__ ams,
                                     const float* __restrict__ amo) {
    const int bx = blockIdx.x;
    if (bx < XCONV_BLOCKS) {
        size_t i = ((size_t)bx * 256 + threadIdx.x) * 2;  // two float4 each
        const float4* xin = reinterpret_cast<const float4*>(x);
        float4 v0 = xin[i];
        float4 v1 = xin[i + 1];
        __half2 a0 = __floats2half2_rn(v0.x, v0.y);
        __half2 b0 = __floats2half2_rn(v0.z, v0.w);
        __half2 a1 = __floats2half2_rn(v1.x, v1.y);
        __half2 b1 = __floats2half2_rn(v1.z, v1.w);
        uint4 o;
        o.x = *reinterpret_cast<unsigned*>(&a0);
        o.y = *reinterpret_cast<unsigned*>(&b0);
        o.z = *reinterpret_cast<unsigned*>(&a1);
        o.w = *reinterpret_cast<unsigned*>(&b1);
        reinterpret_cast<uint4*>(g_X16)[(size_t)bx * 256 + threadIdx.x] = o;
    } else {
        __shared__ float lut[16];
        if (threadIdx.x < 16) lut[threadIdx.x] = c_nf4[threadIdx.x];
        __syncthreads();

        int gid = (bx - XCONV_BLOCKS) * 256 + threadIdx.x;  // 8 codes each
        int b = gid >> 3;                        // 64-elem block index
        float am = fmaf((float)amc[b] * (1.0f / 255.0f), ams[b >> 8], amo[0]);

        const int4* c4 = reinterpret_cast<const int4*>(codes) + (size_t)gid * 2;
        int4 c0 = c4[0];
        int4 c1 = c4[1];

        __half2 p0 = __floats2half2_rn(lut[c0.x] * am, lut[c0.y] * am);
        __half2 p1 = __floats2half2_rn(lut[c0.z] * am, lut[c0.w] * am);
        __half2 p2 = __floats2half2_rn(lut[c1.x] * am, lut[c1.y] * am);
        __half2 p3 = __floats2half2_rn(lut[c1.z] * am, lut[c1.w] * am);

        uint4 o;
        o.x = *reinterpret_cast<unsigned*>(&p0);
        o.y = *reinterpret_cast<unsigned*>(&p1);
        o.z = *reinterpret_cast<unsigned*>(&p2);
        o.w = *reinterpret_cast<unsigned*>(&p3);
        reinterpret_cast<uint4*>(g_W16)[gid] = o;
    }
}

// ---------------------------------------------------------------------------
// Kernel 2: mma.sync GEMM  out[M,N] = X16[M,K] * W16[N,K]^T + bias
//   CTA 128x128x64, 4 warps (2x2), warp tile 64x64, 3-stage cp.async,
//   2 CTAs/SM. Round-12 schedule (the proven winner): wait<1> + barrier at
//   iteration top, LDSM batch per ks, cp.async halves issued after the ks0
//   and ks1 mma batches (hidden under tensor-pipe drain). 2-D grid.
// ---------------------------------------------------------------------------
__device__ __forceinline__ void load_half(uint32_t st, int tid,
                                          const __half* __restrict__ g) {
#pragma unroll
    for (int j = 0; j < 8; j++) {                 // 128 rows x 128B
        int c = tid + j * THREADS;
        int row = c >> 3, kk = c & 7;
        uint32_t sw = (uint32_t)(row * 128) + ((uint32_t)(kk ^ (row & 7)) * 16);
        cp_async16(st + sw, g + (size_t)row * DIM_K + kk * 8);
    }
}

__global__ __launch_bounds__(THREADS, 2)
void gemm_kernel(const float* __restrict__ bias, float* __restrict__ out) {
    extern __shared__ __align__(1024) char smem[];
    const uint32_t smem_base = smem_u32(smem);
    const int tid = threadIdx.x;
    const int wid = tid >> 5, lane = tid & 31;
    const int warpM = wid & 1;         // 0..1, 64 rows each
    const int warpN = wid >> 1;        // 0..1, 64 cols each
    const int mBase = blockIdx.y * BM;
    const int nBase = blockIdx.x * BN;

    const __half* gA = g_X16 + (size_t)mBase * DIM_K;
    const __half* gB = g_W16 + (size_t)nBase * DIM_K;

    // per-thread ldmatrix row/half decomposition
    const uint32_t rowA = (uint32_t)(warpM * 64 + (lane & 15));
    const uint32_t halfA = (uint32_t)(lane >> 4);
    const uint32_t swzA = rowA & 7;
    const uint32_t rowB = (uint32_t)(warpN * 64 + (lane & 7) + 8 * (lane >> 4));
    const uint32_t halfB = (uint32_t)((lane >> 3) & 1);
    const uint32_t swzB = rowB & 7;

    float acc[4][8][4];                 // [mt][nt][frag] : 64x64 per warp
#pragma unroll
    for (int mt = 0; mt < 4; mt++)
#pragma unroll
        for (int nt = 0; nt < 8; nt++)
#pragma unroll
            for (int j = 0; j < 4; j++) acc[mt][nt][j] = 0.0f;

    // prologue: fill STAGES-1 stages
#pragma unroll
    for (int s = 0; s < STAGES - 1; s++) {
        const uint32_t st = smem_base + (uint32_t)s * STAGE_BYTES;
        load_half(st, tid, gA + s * BK);
        load_half(st + STAGE_A_BYTES, tid, gB + s * BK);
        cp_commit();
    }

    int s_comp = 0;                     // stage being computed (mod 3)
    int s_load = STAGES - 1;            // stage being filled   (mod 3)
    for (int it = 0; it < NKITER; it++) {
        cp_wait_group<STAGES - 2>();
        __syncthreads();

        const uint32_t stA = smem_base + (uint32_t)s_comp * STAGE_BYTES;
        const uint32_t stB = stA + STAGE_A_BYTES;
        if (++s_comp == STAGES) s_comp = 0;

        const uint32_t stL = smem_base + (uint32_t)s_load * STAGE_BYTES;
        const int ktL = it + STAGES - 1;
        const bool doLoad = ktL < NKITER;
        if (++s_load == STAGES) s_load = 0;

        uint32_t afrag[4][4];
        uint32_t bfrag[4][4];

#pragma unroll
        for (int ks = 0; ks < 4; ks++) {
            // frag loads for this ks (ks0 right after barrier; ks>0 hidden
            // under previous batch drain)
#pragma unroll
            for (int mt = 0; mt < 4; mt++) {
                uint32_t row = rowA + (uint32_t)(mt * 16);
                uint32_t addr = stA + row * 128 +
                                (((uint32_t)(ks * 2) + halfA) ^ swzA) * 16;
                ldmatrix_x4(afrag[mt], addr);
            }
#pragma unroll
            for (int i = 0; i < 4; i++) {
                uint32_t row = rowB + (uint32_t)(i * 16);
                uint32_t addr = stB + row * 128 +
                                (((uint32_t)(ks * 2) + halfB) ^ swzB) * 16;
                ldmatrix_x4(bfrag[i], addr);
            }
#pragma unroll
            for (int mt = 0; mt < 4; mt++) {
#pragma unroll
                for (int nt = 0; nt < 8; nt++) {
                    mma_16816(acc[mt][nt], afrag[mt],
                              bfrag[nt >> 1][(nt & 1) * 2],
                              bfrag[nt >> 1][(nt & 1) * 2 + 1]);
                }
            }
            // cp.async bursts AFTER a full mma batch: the tensor pipe drains
            // the batch (via issue backpressure) while the LSU issues these
            if (ks == 0 && doLoad)
                load_half(stL, tid, gA + ktL * BK);
            if (ks == 1) {
                if (doLoad)
                    load_half(stL + STAGE_A_BYTES, tid, gB + ktL * BK);
                cp_commit();            // one commit per iter, full stage
            }
        }
    }

    // ------------------ epilogue: bias + direct float2 stores ---------------
#pragma unroll
    for (int nt = 0; nt < 8; nt++) {
        const int col0 = nBase + warpN * 64 + nt * 8 + (lane & 3) * 2;
        const float2 bv = *reinterpret_cast<const float2*>(bias + col0);
#pragma unroll
        for (int mt = 0; mt < 4; mt++) {
            const int row0 = mBase + warpM * 64 + mt * 16 + (lane >> 2);
            float2 v0 = make_float2(acc[mt][nt][0] + bv.x, acc[mt][nt][1] + bv.y);
            float2 v1 = make_float2(acc[mt][nt][2] + bv.x, acc[mt][nt][3] + bv.y);
            *reinterpret_cast<float2*>(out + (size_t)row0 * DIM_N + col0) = v0;
            *reinterpret_cast<float2*>(out + (size_t)(row0 + 8) * DIM_N + col0) = v1;
        }
    }
}

// ---------------------------------------------------------------------------
// Launch
// ---------------------------------------------------------------------------
extern "C" void kernel_launch(void* const* d_in, const int* in_sizes, int n_in,
                              void* d_out, int out_size) {
    const float* x       = (const float*)d_in[0];
    const int*   w_codes = (const int*)  d_in[1];
    const int*   amc     = (const int*)  d_in[2];
    const float* ams     = (const float*)d_in[3];
    const float* amo     = (const float*)d_in[4];
    const float* bias    = (const float*)d_in[5];
    float* out = (float*)d_out;

    convert_fused_kernel<<<XCONV_BLOCKS + WDEQ_BLOCKS, 256>>>(x, w_codes, amc,
                                                              ams, amo);

    static int smem_set = 0;
    if (!smem_set) {
        cudaFuncSetAttribute(gemm_kernel,
                             cudaFuncAttributeMaxDynamicSharedMemorySize,
                             SMEM_TOTAL);
        smem_set = 1;
    }
    dim3 grid(DIM_N / BN, DIM_M / BM);
    gemm_kernel<<<grid, THREADS, SMEM_TOTAL>>>(bias, out);
}